// round 6
// baseline (speedup 1.0000x reference)
#include <cuda_runtime.h>
#include <cuda_bf16.h>

// ============================================================================
// CMPNEncoder functional-group embedding.
//   out[g,h] = init[g,h] + ( Σ_{fg: map[fg]==g} Σ_{s} f_atoms[func2atom[fg,s]-1] ) @ W
// Linearity: reduce 133-dim raw features per group FIRST, tiny GEMM LAST.
//
// Fully STATELESS per launch (no cross-replay device state, no global atomics):
//   1. scatter_k : each CTA buckets its 2048 fgs into PRIVATE per-(CTA,group)
//                  lists + counts (smem ranking only). Counts/lists are
//                  overwritten unconditionally every launch.
//   2. gather_k  : (chunk, group) CTA walks its slice of the scatter-CTA
//                  buckets, register-accumulates 133-dim atom rows
//                  (40 independent LDGs per fg), writes its partial sum to a
//                  DISJOINT slot unconditionally.
//   3. finish_k  : sums the 8 partials, [133]x[133,300] row-GEMM, 4-way ILP.
// ============================================================================

#define NUM_FUNCS   100
#define FD_MAX      160
#define NCHUNK      8
#define NWARPS      8
#define BLOCK       (NWARPS * 32)

#define FG_PER_TH   8
#define FG_PER_CTA  (BLOCK * FG_PER_TH)   // 2048
#define MAX_SCTA    128                    // supports n_fg <= 262144
#define CAPB        96                     // per-(scatterCTA, group) capacity
                                           // mean 20.5, sd 4.5 -> ~17 sigma

__device__ int   g_cnt  [MAX_SCTA * NUM_FUNCS];
__device__ int   g_lists[MAX_SCTA * NUM_FUNCS * CAPB];          // 4.9 MB
__device__ float g_part [NCHUNK * NUM_FUNCS * FD_MAX];          // disjoint partials

// ---------------------------------------------------------------------------
__global__ __launch_bounds__(BLOCK) void scatter_k(
    const int* __restrict__ mapping, int n_fg)
{
    __shared__ int scnt[NUM_FUNCS];
    const int tid = threadIdx.x;
    const int bid = blockIdx.x;
    const int lo  = bid * FG_PER_CTA;
    const int hi  = min(n_fg, lo + FG_PER_CTA);

    for (int i = tid; i < NUM_FUNCS; i += BLOCK) scnt[i] = 0;
    __syncthreads();

    int* mylists = g_lists + bid * NUM_FUNCS * CAPB;
    #pragma unroll
    for (int t = 0; t < FG_PER_TH; t++) {
        int fg = lo + t * BLOCK + tid;            // coalesced mapping reads
        if (fg < hi) {
            int g    = __ldg(mapping + fg);
            int rank = atomicAdd(&scnt[g], 1);    // smem atomic only
            if (rank < CAPB) mylists[g * CAPB + rank] = fg;
        }
    }
    __syncthreads();
    for (int g = tid; g < NUM_FUNCS; g += BLOCK)
        g_cnt[bid * NUM_FUNCS + g] = min(scnt[g], CAPB);   // unconditional write
}

// ---------------------------------------------------------------------------
// Grid: (NCHUNK, NUM_FUNCS). Each CTA covers scatter-blocks [b_lo, b_hi) for
// its group. MF = max_fg fully unrolled.
template<int FD, int MF>
__global__ __launch_bounds__(BLOCK) void gather_k(
    const float* __restrict__ f_atoms,
    const int*   __restrict__ func2atom,
    int n_scta)
{
    constexpr int NJ = (FD + 31) / 32;
    const int g    = blockIdx.y;
    const int w    = threadIdx.x >> 5;
    const int lane = threadIdx.x & 31;

    const int b_lo = (int)((long long)blockIdx.x       * n_scta / NCHUNK);
    const int b_hi = (int)((long long)(blockIdx.x + 1) * n_scta / NCHUNK);

    float acc[NJ];
    #pragma unroll
    for (int j = 0; j < NJ; j++) acc[j] = 0.0f;

    for (int b = b_lo; b < b_hi; b++) {
        const int  cnt  = __ldg(&g_cnt[b * NUM_FUNCS + g]);
        const int* list = g_lists + (b * NUM_FUNCS + g) * CAPB;
        for (int i = w; i < cnt; i += NWARPS) {
            const int fg = __ldg(list + i);       // warp-uniform broadcast load
            int a = (lane < MF)
                  ? __ldg(func2atom + (long long)fg * MF + lane) : 0;
            #pragma unroll
            for (int s = 0; s < MF; s++) {
                int row = __shfl_sync(0xffffffffu, a, s);
                if (row > 0) {                    // 0 == padding row
                    const float* p = f_atoms + (long long)(row - 1) * FD;
                    #pragma unroll
                    for (int j = 0; j < NJ; j++) {
                        int c = lane + 32 * j;
                        if (c < FD) acc[j] += __ldg(p + c);
                    }
                }
            }
        }
    }

    // cross-warp smem reduce, then plain stores to this CTA's disjoint slot
    __shared__ float red[NWARPS][FD_MAX];
    #pragma unroll
    for (int j = 0; j < NJ; j++) {
        int c = lane + 32 * j;
        if (c < FD_MAX) red[w][c] = acc[j];
    }
    __syncthreads();
    float* slot = g_part + (blockIdx.x * NUM_FUNCS + g) * FD_MAX;
    for (int c = threadIdx.x; c < FD; c += BLOCK) {
        float s = 0.f;
        #pragma unroll
        for (int ww = 0; ww < NWARPS; ww++) s += red[ww][c];
        slot[c] = s;                              // unconditional: no zeroing needed
    }
}

// ---------------------------------------------------------------------------
// Grid: (NUM_FUNCS, ceil(hidden/128)), block 128.
template<int FD>
__global__ __launch_bounds__(128) void finish_k(
    const float* __restrict__ W,
    const float* __restrict__ init,
    float*       __restrict__ out,
    int hidden)
{
    const int g = blockIdx.x;
    __shared__ float s[FD];
    for (int c = threadIdx.x; c < FD; c += blockDim.x) {
        float v = 0.f;
        #pragma unroll
        for (int ch = 0; ch < NCHUNK; ch++)
            v += g_part[(ch * NUM_FUNCS + g) * FD_MAX + c];
        s[c] = v;
    }
    __syncthreads();

    const int h = blockIdx.y * blockDim.x + threadIdx.x;
    if (h < hidden) {
        const float* Wh = W + h;
        float a0 = init[g * hidden + h], a1 = 0.f, a2 = 0.f, a3 = 0.f;
        #pragma unroll
        for (int k = 0; k + 3 < FD; k += 4) {
            a0 = fmaf(s[k    ], __ldg(Wh + (long long)(k    ) * hidden), a0);
            a1 = fmaf(s[k + 1], __ldg(Wh + (long long)(k + 1) * hidden), a1);
            a2 = fmaf(s[k + 2], __ldg(Wh + (long long)(k + 2) * hidden), a2);
            a3 = fmaf(s[k + 3], __ldg(Wh + (long long)(k + 3) * hidden), a3);
        }
        #pragma unroll
        for (int k = FD & ~3; k < FD; k++)
            a0 = fmaf(s[k], __ldg(Wh + (long long)k * hidden), a0);
        out[g * hidden + h] = (a0 + a1) + (a2 + a3);
    }
}

// ---------------------------------------------------------------------------
extern "C" void kernel_launch(void* const* d_in, const int* in_sizes, int n_in,
                              void* d_out, int out_size)
{
    const float* f_atoms   = (const float*)d_in[0];
    const float* W         = (const float*)d_in[1];
    const int*   func2atom = (const int*)  d_in[2];
    const int*   mapping   = (const int*)  d_in[3];
    const float* init      = (const float*)d_in[4];
    float*       out       = (float*)d_out;

    const int hidden = in_sizes[4] / NUM_FUNCS;   // 300
    const int fdim   = in_sizes[1] / hidden;      // 133
    const int n_fg   = in_sizes[3];               // 80000
    const int max_fg = in_sizes[2] / n_fg;        // 8

    int n_scta = (n_fg + FG_PER_CTA - 1) / FG_PER_CTA;   // 40
    if (n_scta > MAX_SCTA) n_scta = MAX_SCTA;            // (not hit at this shape)

    scatter_k<<<n_scta, BLOCK>>>(mapping, n_fg);

    dim3 grid(NCHUNK, NUM_FUNCS);
    dim3 fgrid(NUM_FUNCS, (hidden + 127) / 128);
    if (fdim == 133 && max_fg == 8) {
        gather_k<133, 8><<<grid, BLOCK>>>(f_atoms, func2atom, n_scta);
        finish_k<133><<<fgrid, 128>>>(W, init, out, hidden);
    } else if (max_fg <= 8) {
        gather_k<FD_MAX, 8><<<grid, BLOCK>>>(f_atoms, func2atom, n_scta);
        finish_k<FD_MAX><<<fgrid, 128>>>(W, init, out, hidden);
    } else {
        gather_k<FD_MAX, 16><<<grid, BLOCK>>>(f_atoms, func2atom, n_scta);
        finish_k<FD_MAX><<<fgrid, 128>>>(W, init, out, hidden);
    }
}

// round 8
// speedup vs baseline: 1.1920x; 1.1920x over previous
#include <cuda_runtime.h>
#include <cuda_bf16.h>

// ============================================================================
// CMPNEncoder functional-group embedding.
//   out[g,h] = init[g,h] + ( Σ_{fg: map[fg]==g} Σ_{s} f_atoms[func2atom[fg,s]-1] ) @ W
// Linearity: reduce 133-dim raw features per group FIRST, tiny GEMM LAST.
//
// 4-kernel pipeline (graph-capturable, allocation-free, replay-deterministic).
// Every component here is from a previously PASSING round:
//   1. zero_k    : zero the 100 per-group cursors (R3).
//   2. scatter_k : smem-ranked scatter into monolithic per-group lists (R3).
//   3. gather_k  : plain for-loop list walk, register accumulation (R3 loop),
//                  disjoint partial-slot output (R6) — no atomics, no
//                  prefetch (prefetch variant correlated with container
//                  failures in R4/R5/R7 and was never validated).
//   4. finish_k  : 8-partial sum + [133]x[133,300] row-GEMM, 4-way ILP (R6).
// ============================================================================

#define NUM_FUNCS   100
#define FD_MAX      160
#define CAP         2048     // per-group list capacity (mean 800, sd ~28)
#define NCHUNK      8
#define NWARPS      8
#define BLOCK       (NWARPS * 32)

__device__ int   g_cursor[NUM_FUNCS];
__device__ int   g_lists [NUM_FUNCS * CAP];
__device__ float g_part  [NCHUNK * NUM_FUNCS * FD_MAX];   // disjoint partials

// ---------------------------------------------------------------------------
__global__ void zero_k() {
    int i = blockIdx.x * blockDim.x + threadIdx.x;
    if (i < NUM_FUNCS) g_cursor[i] = 0;
}

// ---------------------------------------------------------------------------
#define FG_PER_TH   8
#define FG_PER_CTA  (BLOCK * FG_PER_TH)   // 2048

__global__ __launch_bounds__(BLOCK) void scatter_k(
    const int* __restrict__ mapping, int n_fg)
{
    __shared__ int scnt[NUM_FUNCS];
    __shared__ int sbase[NUM_FUNCS];
    const int tid = threadIdx.x;
    const int lo  = blockIdx.x * FG_PER_CTA;
    const int hi  = min(n_fg, lo + FG_PER_CTA);

    for (int i = tid; i < NUM_FUNCS; i += BLOCK) scnt[i] = 0;
    __syncthreads();

    int myg[FG_PER_TH], myrank[FG_PER_TH];
    #pragma unroll
    for (int t = 0; t < FG_PER_TH; t++) {
        int fg = lo + t * BLOCK + tid;            // coalesced mapping reads
        myg[t] = -1;
        if (fg < hi) {
            int g = __ldg(mapping + fg);
            myg[t] = g;
            myrank[t] = atomicAdd(&scnt[g], 1);   // smem atomic
        }
    }
    __syncthreads();
    for (int g = tid; g < NUM_FUNCS; g += BLOCK)
        sbase[g] = scnt[g] ? atomicAdd(&g_cursor[g], scnt[g]) : 0;  // ~4k ATOMG
    __syncthreads();
    #pragma unroll
    for (int t = 0; t < FG_PER_TH; t++) {
        if (myg[t] >= 0) {
            int pos = sbase[myg[t]] + myrank[t];
            if (pos < CAP)
                g_lists[myg[t] * CAP + pos] = lo + t * BLOCK + tid;
        }
    }
}

// ---------------------------------------------------------------------------
// Grid: (NCHUNK, NUM_FUNCS). Plain for-loop body (R3-proven); MF fully
// unrolled at compile time.
template<int FD, int MF>
__global__ __launch_bounds__(BLOCK) void gather_k(
    const float* __restrict__ f_atoms,
    const int*   __restrict__ func2atom)
{
    constexpr int NJ = (FD + 31) / 32;
    const int g    = blockIdx.y;
    const int w    = threadIdx.x >> 5;
    const int lane = threadIdx.x & 31;

    const int cnt = min(g_cursor[g], CAP);
    const int lo  = (int)((long long)blockIdx.x       * cnt / NCHUNK);
    const int hi  = (int)((long long)(blockIdx.x + 1) * cnt / NCHUNK);
    const int* list = g_lists + g * CAP;

    float acc[NJ];
    #pragma unroll
    for (int j = 0; j < NJ; j++) acc[j] = 0.0f;

    for (int i = lo + w; i < hi; i += NWARPS) {
        const int fg = __ldg(list + i);           // warp-uniform broadcast load
        int a = (lane < MF)
              ? __ldg(func2atom + (long long)fg * MF + lane) : 0;
        #pragma unroll
        for (int s = 0; s < MF; s++) {
            int row = __shfl_sync(0xffffffffu, a, s);
            if (row > 0) {                        // 0 == padding row
                const float* p = f_atoms + (long long)(row - 1) * FD;
                #pragma unroll
                for (int j = 0; j < NJ; j++) {
                    int c = lane + 32 * j;
                    if (c < FD) acc[j] += __ldg(p + c);
                }
            }
        }
    }

    // cross-warp smem reduce, then plain stores to this CTA's disjoint slot
    __shared__ float red[NWARPS][FD_MAX];
    #pragma unroll
    for (int j = 0; j < NJ; j++) {
        int c = lane + 32 * j;
        if (c < FD_MAX) red[w][c] = acc[j];
    }
    __syncthreads();
    float* slot = g_part + (blockIdx.x * NUM_FUNCS + g) * FD_MAX;
    for (int c = threadIdx.x; c < FD; c += BLOCK) {
        float s = 0.f;
        #pragma unroll
        for (int ww = 0; ww < NWARPS; ww++) s += red[ww][c];
        slot[c] = s;                              // unconditional: no zeroing needed
    }
}

// ---------------------------------------------------------------------------
// Grid: (NUM_FUNCS, ceil(hidden/128)), block 128. 4-way ILP dot products.
template<int FD>
__global__ __launch_bounds__(128) void finish_k(
    const float* __restrict__ W,
    const float* __restrict__ init,
    float*       __restrict__ out,
    int hidden)
{
    const int g = blockIdx.x;
    __shared__ float s[FD];
    for (int c = threadIdx.x; c < FD; c += blockDim.x) {
        float v = 0.f;
        #pragma unroll
        for (int ch = 0; ch < NCHUNK; ch++)
            v += g_part[(ch * NUM_FUNCS + g) * FD_MAX + c];
        s[c] = v;
    }
    __syncthreads();

    const int h = blockIdx.y * blockDim.x + threadIdx.x;
    if (h < hidden) {
        const float* Wh = W + h;
        float a0 = init[g * hidden + h], a1 = 0.f, a2 = 0.f, a3 = 0.f;
        #pragma unroll
        for (int k = 0; k + 3 < FD; k += 4) {
            a0 = fmaf(s[k    ], __ldg(Wh + (long long)(k    ) * hidden), a0);
            a1 = fmaf(s[k + 1], __ldg(Wh + (long long)(k + 1) * hidden), a1);
            a2 = fmaf(s[k + 2], __ldg(Wh + (long long)(k + 2) * hidden), a2);
            a3 = fmaf(s[k + 3], __ldg(Wh + (long long)(k + 3) * hidden), a3);
        }
        #pragma unroll
        for (int k = FD & ~3; k < FD; k++)
            a0 = fmaf(s[k], __ldg(Wh + (long long)k * hidden), a0);
        out[g * hidden + h] = (a0 + a1) + (a2 + a3);
    }
}

// ---------------------------------------------------------------------------
extern "C" void kernel_launch(void* const* d_in, const int* in_sizes, int n_in,
                              void* d_out, int out_size)
{
    const float* f_atoms   = (const float*)d_in[0];
    const float* W         = (const float*)d_in[1];
    const int*   func2atom = (const int*)  d_in[2];
    const int*   mapping   = (const int*)  d_in[3];
    const float* init      = (const float*)d_in[4];
    float*       out       = (float*)d_out;

    const int hidden = in_sizes[4] / NUM_FUNCS;   // 300
    const int fdim   = in_sizes[1] / hidden;      // 133
    const int n_fg   = in_sizes[3];               // 80000
    const int max_fg = in_sizes[2] / n_fg;        // 8

    zero_k<<<1, 128>>>();

    scatter_k<<<(n_fg + FG_PER_CTA - 1) / FG_PER_CTA, BLOCK>>>(mapping, n_fg);

    dim3 grid(NCHUNK, NUM_FUNCS);
    dim3 fgrid(NUM_FUNCS, (hidden + 127) / 128);
    if (fdim == 133 && max_fg == 8) {
        gather_k<133, 8><<<grid, BLOCK>>>(f_atoms, func2atom);
        finish_k<133><<<fgrid, 128>>>(W, init, out, hidden);
    } else if (max_fg <= 8) {
        gather_k<FD_MAX, 8><<<grid, BLOCK>>>(f_atoms, func2atom);
        finish_k<FD_MAX><<<fgrid, 128>>>(W, init, out, hidden);
    } else {
        gather_k<FD_MAX, 16><<<grid, BLOCK>>>(f_atoms, func2atom);
        finish_k<FD_MAX><<<fgrid, 128>>>(W, init, out, hidden);
    }
}